// round 8
// baseline (speedup 1.0000x reference)
#include <cuda_runtime.h>
#include <cstdint>

// NetVLAD fused pool via 3-product BF16 mma.sync (m16n8k16), sm_103a. Round 7.
// Grid = 1024 CTAs = (m, s); 4 tiles of 128 rows. R stored twice in smem as
// bf16x2 hi/lo: Rc packed over c (stage A k-dim), Rn packed over n (stage B k-dim).
// A' packed over n via shfl. 3 products (hh, hl, lh) ~= fp32 accuracy.

#define MMA_BF16(d0,d1,d2,d3, a0,a1,a2,a3, b0,b1) \
  asm volatile("mma.sync.aligned.m16n8k16.row.col.f32.bf16.bf16.f32 " \
      "{%0,%1,%2,%3},{%4,%5,%6,%7},{%8,%9},{%0,%1,%2,%3};" \
      : "+f"(d0),"+f"(d1),"+f"(d2),"+f"(d3) \
      : "r"(a0),"r"(a1),"r"(a2),"r"(a3),"r"(b0),"r"(b1))

__device__ __forceinline__ void splitb(float x, uint32_t& h, uint32_t& l) {
    h = __float_as_uint(x) & 0xFFFF0000u;
    float lf = x - __uint_as_float(h);
    l = __float_as_uint(lf) & 0xFFFF0000u;
}
__device__ __forceinline__ uint32_t packb(uint32_t xh, uint32_t yh) {
    return (xh >> 16) | (yh & 0xFFFF0000u);   // x -> low half (even idx), y -> high
}

namespace {
constexpr int Nn = 2048, Cc = 64, Kk = 32;
constexpr int SPLIT = 4, NT = 128;
constexpr int TILES = (Nn / SPLIT) / NT;   // 4
constexpr int RCP = 36;   // Rc pitch (cpairs)
constexpr int RNP = 72;   // Rn pitch (c words)  -- 72 for CF 8q+g banks
constexpr int WCP = 36;   // Wc pitch (cpairs)
constexpr int AKP = 68;   // Ak pitch (npairs)
constexpr int O_RCH = 0;
constexpr int O_RCL = O_RCH + NT * RCP;          // 4608
constexpr int O_RNH = O_RCL + NT * RCP;          // 9216
constexpr int O_RNL = O_RNH + 64 * RNP;          // 13824
constexpr int O_WCH = O_RNL + 64 * RNP;          // 18432
constexpr int O_WCL = O_WCH + Kk * WCP;
constexpr int O_AKH = O_WCL + Kk * WCP;
constexpr int O_AKL = O_AKH + Kk * AKP;
constexpr int O_AS  = O_AKL + Kk * AKP;
constexpr int SMEM_BYTES = (O_AS + 32) * 4;      // ~100.5 KB -> 2 CTAs/SM
}

__global__ void nv_zero(float4* __restrict__ out, int n4) {
    int i = blockIdx.x * blockDim.x + threadIdx.x;
    if (i < n4) out[i] = make_float4(0.f, 0.f, 0.f, 0.f);
}

__global__ __launch_bounds__(256, 2) void nv_tc(
    const float* __restrict__ R, const float* __restrict__ W,
    const float* __restrict__ bvec, const float* __restrict__ cent,
    float* __restrict__ out)
{
    extern __shared__ float sm[];
    uint32_t* RCH = (uint32_t*)(sm + O_RCH);
    uint32_t* RCL = (uint32_t*)(sm + O_RCL);
    uint32_t* RNH = (uint32_t*)(sm + O_RNH);
    uint32_t* RNL = (uint32_t*)(sm + O_RNL);
    uint32_t* WCH = (uint32_t*)(sm + O_WCH);
    uint32_t* WCL = (uint32_t*)(sm + O_WCL);
    uint32_t* AKH = (uint32_t*)(sm + O_AKH);
    uint32_t* AKL = (uint32_t*)(sm + O_AKL);
    float* asum_sm = sm + O_AS;

    const int t    = threadIdx.x;
    const int m    = blockIdx.x >> 2;
    const int s    = blockIdx.x & 3;
    const int w    = t >> 5;
    const int lane = t & 31;
    const int g    = lane >> 2;
    const int q    = lane & 3;
    const bool evenlane = (lane & 4) == 0;   // g even

    if (t < 32) asum_sm[t] = 0.f;

    // W (K=32, C=64) -> bf16x2 hi/lo packed over c pairs
    #pragma unroll
    for (int i = 0; i < 4; i++) {
        int idx = i * 256 + t;              // pair index: k*32 + cp
        int k = idx >> 5, cp = idx & 31;
        float2 wv = ((const float2*)W)[idx];
        uint32_t xh, xl, yh, yl;
        splitb(wv.x, xh, xl); splitb(wv.y, yh, yl);
        WCH[k * WCP + cp] = packb(xh, yh);
        WCL[k * WCP + cp] = packb(xl, yl);
    }

    float bias[4][2];
    #pragma unroll
    for (int nb = 0; nb < 4; nb++) {
        bias[nb][0] = bvec[8 * nb + 2 * q];
        bias[nb][1] = bvec[8 * nb + 2 * q + 1];
    }

    const int kb  = w & 1;
    const int cb0 = (w >> 1) * 16;
    const int rb  = 16 * w;
    const int col4 = t & 15;     // loader: float4 column
    const int rp0  = t >> 4;     // loader: base rowpair

    float vA[2][4];
    float asl[4][2];
    #pragma unroll
    for (int cb = 0; cb < 2; cb++)
        #pragma unroll
        for (int r = 0; r < 4; r++) vA[cb][r] = 0.f;
    #pragma unroll
    for (int nb = 0; nb < 4; nb++) { asl[nb][0] = 0.f; asl[nb][1] = 0.f; }

    const float* Rbase = R + ((size_t)m * Nn + (size_t)s * (Nn / SPLIT)) * Cc;

    // prefetch tile 0: per j, rows 2rp and 2rp+1, float4 col4 (coalesced 512B/warp)
    float4 pfa[4], pfb[4];
    {
        const float4* Rg = (const float4*)Rbase;
        #pragma unroll
        for (int j = 0; j < 4; j++) {
            int rp = rp0 + 16 * j;
            pfa[j] = Rg[(2 * rp) * 16 + col4];
            pfb[j] = Rg[(2 * rp + 1) * 16 + col4];
        }
    }

    for (int tile = 0; tile < TILES; ++tile) {
        if (tile > 0) __syncthreads();   // prior stage A/B done with Rc/Rn/Ak

        // ---- split + dual-layout store (in-register, no shuffles)
        #pragma unroll
        for (int j = 0; j < 4; j++) {
            const int rp = rp0 + 16 * j;
            uint32_t ah[4], al[4], bh[4], bl[4];
            splitb(pfa[j].x, ah[0], al[0]); splitb(pfa[j].y, ah[1], al[1]);
            splitb(pfa[j].z, ah[2], al[2]); splitb(pfa[j].w, ah[3], al[3]);
            splitb(pfb[j].x, bh[0], bl[0]); splitb(pfb[j].y, bh[1], bl[1]);
            splitb(pfb[j].z, bh[2], bl[2]); splitb(pfb[j].w, bh[3], bl[3]);
            // Rc: rows 2rp, 2rp+1; cpairs 2*col4, 2*col4+1
            *(uint2*)(RCH + (2 * rp) * RCP + 2 * col4)     = make_uint2(packb(ah[0],ah[1]), packb(ah[2],ah[3]));
            *(uint2*)(RCL + (2 * rp) * RCP + 2 * col4)     = make_uint2(packb(al[0],al[1]), packb(al[2],al[3]));
            *(uint2*)(RCH + (2 * rp + 1) * RCP + 2 * col4) = make_uint2(packb(bh[0],bh[1]), packb(bh[2],bh[3]));
            *(uint2*)(RCL + (2 * rp + 1) * RCP + 2 * col4) = make_uint2(packb(bl[0],bl[1]), packb(bl[2],bl[3]));
            // Rn: npair rp, c = 4*col4..+3
            uint4 nh, nl;
            nh.x = packb(ah[0], bh[0]); nl.x = packb(al[0], bl[0]);
            nh.y = packb(ah[1], bh[1]); nl.y = packb(al[1], bl[1]);
            nh.z = packb(ah[2], bh[2]); nl.z = packb(al[2], bl[2]);
            nh.w = packb(ah[3], bh[3]); nl.w = packb(al[3], bl[3]);
            *(uint4*)(RNH + rp * RNP + 4 * col4) = nh;
            *(uint4*)(RNL + rp * RNP + 4 * col4) = nl;
        }
        __syncthreads();

        // ---- prefetch next tile
        if (tile + 1 < TILES) {
            const float4* Rg = (const float4*)(Rbase + (size_t)(tile + 1) * NT * Cc);
            #pragma unroll
            for (int j = 0; j < 4; j++) {
                int rp = rp0 + 16 * j;
                pfa[j] = Rg[(2 * rp) * 16 + col4];
                pfb[j] = Rg[(2 * rp + 1) * 16 + col4];
            }
        }

        // ---- Stage A: warp w rows rb..rb+15; D[n][k], 4 c-chunks of 16
        float dA[4][4];
        #pragma unroll
        for (int nb = 0; nb < 4; nb++) {
            dA[nb][0] = bias[nb][0]; dA[nb][1] = bias[nb][1];
            dA[nb][2] = bias[nb][0]; dA[nb][3] = bias[nb][1];
        }
        #pragma unroll
        for (int ch = 0; ch < 4; ch++) {
            const int cpb = 8 * ch;
            const int r0 = (rb + g) * RCP + cpb;
            const int r1 = (rb + g + 8) * RCP + cpb;
            uint32_t Ah0 = RCH[r0 + q],     Al0 = RCL[r0 + q];
            uint32_t Ah1 = RCH[r1 + q],     Al1 = RCL[r1 + q];
            uint32_t Ah2 = RCH[r0 + 4 + q], Al2 = RCL[r0 + 4 + q];
            uint32_t Ah3 = RCH[r1 + 4 + q], Al3 = RCL[r1 + 4 + q];
            #pragma unroll
            for (int nb = 0; nb < 4; nb++) {
                const int kr = (8 * nb + g) * WCP + cpb;
                uint32_t Bh0 = WCH[kr + q], Bh1 = WCH[kr + 4 + q];
                uint32_t Bl0 = WCL[kr + q], Bl1 = WCL[kr + 4 + q];
                MMA_BF16(dA[nb][0],dA[nb][1],dA[nb][2],dA[nb][3],
                         Ah0,Ah1,Ah2,Ah3, Bh0,Bh1);
                MMA_BF16(dA[nb][0],dA[nb][1],dA[nb][2],dA[nb][3],
                         Ah0,Ah1,Ah2,Ah3, Bl0,Bl1);
                MMA_BF16(dA[nb][0],dA[nb][1],dA[nb][2],dA[nb][3],
                         Al0,Al1,Al2,Al3, Bh0,Bh1);
            }
        }

        // ---- softmax over k (rows rb+g, rb+g+8)
        float mx0 = -1e30f, mx1 = -1e30f;
        #pragma unroll
        for (int nb = 0; nb < 4; nb++) {
            mx0 = fmaxf(mx0, fmaxf(dA[nb][0], dA[nb][1]));
            mx1 = fmaxf(mx1, fmaxf(dA[nb][2], dA[nb][3]));
        }
        mx0 = fmaxf(mx0, __shfl_xor_sync(0xffffffffu, mx0, 1));
        mx0 = fmaxf(mx0, __shfl_xor_sync(0xffffffffu, mx0, 2));
        mx1 = fmaxf(mx1, __shfl_xor_sync(0xffffffffu, mx1, 1));
        mx1 = fmaxf(mx1, __shfl_xor_sync(0xffffffffu, mx1, 2));
        float s0 = 0.f, s1 = 0.f;
        #pragma unroll
        for (int nb = 0; nb < 4; nb++) {
            dA[nb][0] = __expf(dA[nb][0] - mx0);
            dA[nb][1] = __expf(dA[nb][1] - mx0);
            dA[nb][2] = __expf(dA[nb][2] - mx1);
            dA[nb][3] = __expf(dA[nb][3] - mx1);
            s0 += dA[nb][0] + dA[nb][1];
            s1 += dA[nb][2] + dA[nb][3];
        }
        s0 += __shfl_xor_sync(0xffffffffu, s0, 1);
        s0 += __shfl_xor_sync(0xffffffffu, s0, 2);
        s1 += __shfl_xor_sync(0xffffffffu, s1, 1);
        s1 += __shfl_xor_sync(0xffffffffu, s1, 2);
        const float inv0 = __fdividef(1.f, s0);
        const float inv1 = __fdividef(1.f, s1);
        // pack A' over n: own (even n) + partner lane g^1 (odd n)
        #pragma unroll
        for (int nb = 0; nb < 4; nb++) {
            #pragma unroll
            for (int j = 0; j < 2; j++) {
                const int k = 8 * nb + 2 * q + j;
                float p0 = dA[nb][j]     * inv0;
                float p1 = dA[nb][j + 2] * inv1;
                asl[nb][j] += p0 + p1;
                uint32_t h0, l0, h1, l1;
                splitb(p0, h0, l0);
                splitb(p1, h1, l1);
                uint32_t ph0 = __shfl_xor_sync(0xffffffffu, h0, 4);
                uint32_t pl0 = __shfl_xor_sync(0xffffffffu, l0, 4);
                uint32_t ph1 = __shfl_xor_sync(0xffffffffu, h1, 4);
                uint32_t pl1 = __shfl_xor_sync(0xffffffffu, l1, 4);
                if (evenlane) {
                    const int np0 = (rb + g) >> 1;
                    const int np1 = (rb + g + 8) >> 1;
                    AKH[k * AKP + np0] = packb(h0, ph0);
                    AKL[k * AKP + np0] = packb(l0, pl0);
                    AKH[k * AKP + np1] = packb(h1, ph1);
                    AKL[k * AKP + np1] = packb(l1, pl1);
                }
            }
        }
        __syncthreads();   // A' visible

        // ---- Stage B: D[k][c] += A'[k][n]*R[n][c]; 8 n-chunks of 16
        #pragma unroll 4
        for (int ch = 0; ch < 8; ch++) {
            const int npb = 8 * ch;
            const int a0i = (16 * kb + g) * AKP + npb;
            const int a1i = (16 * kb + g + 8) * AKP + npb;
            uint32_t Ph0 = AKH[a0i + q],     Pl0 = AKL[a0i + q];
            uint32_t Ph1 = AKH[a1i + q],     Pl1 = AKL[a1i + q];
            uint32_t Ph2 = AKH[a0i + 4 + q], Pl2 = AKL[a0i + 4 + q];
            uint32_t Ph3 = AKH[a1i + 4 + q], Pl3 = AKL[a1i + 4 + q];
            #pragma unroll
            for (int cb = 0; cb < 2; cb++) {
                const int c0 = cb0 + 8 * cb;
                const int b0i = (npb + q) * RNP + c0 + g;
                const int b1i = (npb + 4 + q) * RNP + c0 + g;
                uint32_t Rh0 = RNH[b0i], Rl0 = RNL[b0i];
                uint32_t Rh1 = RNH[b1i], Rl1 = RNL[b1i];
                MMA_BF16(vA[cb][0],vA[cb][1],vA[cb][2],vA[cb][3],
                         Ph0,Ph1,Ph2,Ph3, Rh0,Rh1);
                MMA_BF16(vA[cb][0],vA[cb][1],vA[cb][2],vA[cb][3],
                         Ph0,Ph1,Ph2,Ph3, Rl0,Rl1);
                MMA_BF16(vA[cb][0],vA[cb][1],vA[cb][2],vA[cb][3],
                         Pl0,Pl1,Pl2,Pl3, Rh0,Rh1);
            }
        }
    }

    // ---- asum reduce + epilogue (same as R5)
    #pragma unroll
    for (int nb = 0; nb < 4; nb++) {
        #pragma unroll
        for (int j = 0; j < 2; j++) {
            float v = asl[nb][j];
            v += __shfl_xor_sync(0xffffffffu, v, 4);
            v += __shfl_xor_sync(0xffffffffu, v, 8);
            v += __shfl_xor_sync(0xffffffffu, v, 16);
            if (g == 0) atomicAdd(&asum_sm[8 * nb + 2 * q + j], v);
        }
    }
    __syncthreads();

    float* outm = out + (size_t)m * Kk * Cc;
    const int k0 = 16 * kb + g, k1 = k0 + 8;
    const float as0 = asum_sm[k0], as1 = asum_sm[k1];
    #pragma unroll
    for (int cb = 0; cb < 2; cb++) {
        const int c = cb0 + 8 * cb + 2 * q;
        const float2 c0v = *(const float2*)(cent + k0 * 64 + c);
        const float2 c1v = *(const float2*)(cent + k1 * 64 + c);
        atomicAdd(outm + k0 * 64 + c,     vA[cb][0] - as0 * c0v.x);
        atomicAdd(outm + k0 * 64 + c + 1, vA[cb][1] - as0 * c0v.y);
        atomicAdd(outm + k1 * 64 + c,     vA[cb][2] - as1 * c1v.x);
        atomicAdd(outm + k1 * 64 + c + 1, vA[cb][3] - as1 * c1v.y);
    }
}

extern "C" void kernel_launch(void* const* d_in, const int* in_sizes, int n_in,
                              void* d_out, int out_size) {
    const float* R    = (const float*)d_in[0];
    const float* W    = (const float*)d_in[1];
    const float* b    = (const float*)d_in[2];
    const float* cent = (const float*)d_in[3];
    float* out = (float*)d_out;

    cudaFuncSetAttribute(nv_tc, cudaFuncAttributeMaxDynamicSharedMemorySize, SMEM_BYTES);
    int n4 = out_size / 4;
    nv_zero<<<(n4 + 255) / 256, 256>>>((float4*)out, n4);
    nv_tc<<<256 * SPLIT, 256, SMEM_BYTES>>>(R, W, b, cent, out);
}